// round 12
// baseline (speedup 1.0000x reference)
#include <cuda_runtime.h>
#include <cuda_fp16.h>
#include <cstdint>

#define E_ 8
#define D_ 1024
#define F_ 4096
#define T_ 8192
#define TPAD (T_ + E_ * 128)     // 9216: per-expert 128-alignment padding
#define MAX_TILES 80
#define G1BLKS (32 * MAX_TILES)  // GEMM1 blocks in fused launch

#define STAGES 3
#define STAGE_BYTES 32768        // A 16KB (128x64h) + B 16KB (128x64h)
#define SMEM_TOTAL (STAGES * STAGE_BYTES)   // 98304 -> 2 CTAs/SM

// ------------------- scratch (device globals; no runtime allocs) -------------------
__device__ __half g_w1h[(size_t)E_ * F_ * D_];
__device__ __half g_w2h[(size_t)E_ * D_ * F_];
__device__ __half g_hnh[(size_t)TPAD * D_];
__device__ __half g_h1h[(size_t)TPAD * F_];
__device__ float  g_alpha[T_];
__device__ int    g_assign[T_];
__device__ int    g_srt[TPAD];
__device__ int    g_counts[E_];
__device__ int    g_offsets[E_];
__device__ int    g_cursor[E_];
__device__ int    g_tileE[MAX_TILES];
__device__ int    g_tileRow[MAX_TILES];
__device__ int    g_tileEnd[MAX_TILES];
__device__ int    g_numTiles;
__device__ int    g_ready[MAX_TILES];     // GEMM1->GEMM2 per-Mtile counters

// ------------------- ptx helpers -------------------
__device__ __forceinline__ uint32_t smem_u32(const void* p) {
    return (uint32_t)__cvta_generic_to_shared(p);
}
__device__ __forceinline__ void cp16(uint32_t dst, const void* src, bool pred) {
    asm volatile("cp.async.cg.shared.global [%0], [%1], 16, %2;\n"
                 :: "r"(dst), "l"(src), "r"(pred ? 16 : 0));
}
__device__ __forceinline__ void cp_commit() { asm volatile("cp.async.commit_group;\n"); }
template <int N>
__device__ __forceinline__ void cp_wait() { asm volatile("cp.async.wait_group %0;\n" :: "n"(N)); }

__device__ __forceinline__ void ldsm_x4(uint32_t r[4], uint32_t addr) {
    asm volatile("ldmatrix.sync.aligned.m8n8.x4.shared.b16 {%0,%1,%2,%3}, [%4];"
                 : "=r"(r[0]), "=r"(r[1]), "=r"(r[2]), "=r"(r[3]) : "r"(addr));
}

__device__ __forceinline__ void mma_16x8x16(float c[4], const uint32_t a[4], const uint32_t b[2]) {
    asm volatile(
        "mma.sync.aligned.m16n8k16.row.col.f32.f16.f16.f32 "
        "{%0,%1,%2,%3}, {%4,%5,%6,%7}, {%8,%9}, {%0,%1,%2,%3};"
        : "+f"(c[0]), "+f"(c[1]), "+f"(c[2]), "+f"(c[3])
        : "r"(a[0]), "r"(a[1]), "r"(a[2]), "r"(a[3]), "r"(b[0]), "r"(b[1]));
}

// ------------------- init -------------------
__global__ void init_kernel() {
    int i = threadIdx.x;
    if (i < E_) g_counts[i] = 0;
    if (i < MAX_TILES) g_ready[i] = 0;
    if (i + 32 < MAX_TILES) g_ready[i + 32] = 0;
    if (i + 64 < MAX_TILES) g_ready[i + 64] = 0;
}

// ------------------- fp32 -> fp16 weight conversion -------------------
__global__ void convert_kernel(const float* __restrict__ src, int which) {
    __half* dst = which ? g_w2h : g_w1h;
    size_t n4 = ((size_t)E_ * F_ * D_) / 4;
    size_t stride = (size_t)gridDim.x * blockDim.x;
    for (size_t i = (size_t)blockIdx.x * blockDim.x + threadIdx.x; i < n4; i += stride) {
        float4 v = ((const float4*)src)[i];
        ((__half2*)dst)[2 * i]     = __floats2half2_rn(v.x, v.y);
        ((__half2*)dst)[2 * i + 1] = __floats2half2_rn(v.z, v.w);
    }
}

// ------------------- routing -------------------
__global__ void routing_kernel(const float* __restrict__ x, const float* __restrict__ cent) {
    __shared__ float4 sc[E_][D_ / 4];
    int tid = threadIdx.x;
    for (int i = tid; i < E_ * D_ / 4; i += 256)
        ((float4*)&sc[0][0])[i] = ((const float4*)cent)[i];
    __syncthreads();

    int warp = tid >> 5, lane = tid & 31;
    int t = blockIdx.x * 8 + warp;
    const float4* xv = (const float4*)(x + (size_t)t * D_);

    float acc[E_];
#pragma unroll
    for (int e = 0; e < E_; e++) acc[e] = 0.f;
#pragma unroll
    for (int j = 0; j < 8; j++) {
        float4 v = xv[j * 32 + lane];
#pragma unroll
        for (int e = 0; e < E_; e++) {
            float4 c = sc[e][j * 32 + lane];
            acc[e] += v.x * c.x + v.y * c.y + v.z * c.z + v.w * c.w;
        }
    }
#pragma unroll
    for (int e = 0; e < E_; e++) {
#pragma unroll
        for (int off = 16; off > 0; off >>= 1)
            acc[e] += __shfl_xor_sync(0xFFFFFFFFu, acc[e], off);
    }
    if (lane == 0) {
        int best = 0; float bv = acc[0];
#pragma unroll
        for (int e = 1; e < E_; e++)
            if (acc[e] > bv) { bv = acc[e]; best = e; }
        g_assign[t] = best;
        g_alpha[t] = 1.f / (1.f + expf(-bv));
        atomicAdd(&g_counts[best], 1);
    }
}

// ------------------- scan -------------------
__global__ void scan_kernel() {
    if (threadIdx.x != 0) return;
    int off = 0, nt = 0;
    for (int e = 0; e < E_; e++) {
        g_offsets[e] = off;
        g_cursor[e] = off;
        int s1 = off + g_counts[e];
        for (int r = off; r < s1; r += 128) {
            g_tileE[nt]   = e;
            g_tileRow[nt] = r;
            g_tileEnd[nt] = s1;
            nt++;
        }
        off = (s1 + 127) & ~127;
    }
    g_numTiles = nt;
}

// ------------------- layernorm + scatter fused -> fp16 sorted -------------------
__global__ void ln_kernel(const float* __restrict__ x,
                          const float* __restrict__ lng,
                          const float* __restrict__ lnb) {
    int t = blockIdx.x;
    int tid = threadIdx.x;

    __shared__ int sh_s, sh_e;
    if (tid == 0) {
        int e = g_assign[t];
        int s = atomicAdd(&g_cursor[e], 1);
        g_srt[s] = t;
        sh_s = s;
        sh_e = e;
    }

    float4 v = ((const float4*)(x + (size_t)t * D_))[tid];
    float sum = v.x + v.y + v.z + v.w;
    float sq  = v.x * v.x + v.y * v.y + v.z * v.z + v.w * v.w;

    __shared__ float red[2][8];
    int warp = tid >> 5, lane = tid & 31;
#pragma unroll
    for (int off = 16; off > 0; off >>= 1) {
        sum += __shfl_xor_sync(0xFFFFFFFFu, sum, off);
        sq  += __shfl_xor_sync(0xFFFFFFFFu, sq,  off);
    }
    if (lane == 0) { red[0][warp] = sum; red[1][warp] = sq; }
    __syncthreads();
    int s = sh_s, e = sh_e;
    float tot = 0.f, totsq = 0.f;
#pragma unroll
    for (int w = 0; w < 8; w++) { tot += red[0][w]; totsq += red[1][w]; }
    float mu = tot * (1.f / D_);
    float var = totsq * (1.f / D_) - mu * mu;
    float rstd = rsqrtf(var + 1e-5f);

    float4 gg = ((const float4*)(lng + (size_t)e * D_))[tid];
    float4 bb = ((const float4*)(lnb + (size_t)e * D_))[tid];
    __half2 h0 = __floats2half2_rn((v.x - mu) * rstd * gg.x + bb.x,
                                   (v.y - mu) * rstd * gg.y + bb.y);
    __half2 h1 = __floats2half2_rn((v.z - mu) * rstd * gg.z + bb.z,
                                   (v.w - mu) * rstd * gg.w + bb.w);
    __half2* dst = (__half2*)(g_hnh + (size_t)s * D_);
    dst[2 * tid]     = h0;
    dst[2 * tid + 1] = h1;
}

// ===================================================================
// Fused grouped GEMM pair, single launch, 128 threads/CTA.
// bids [0, G1BLKS):    GEMM1 tile (ti = bid>>5, n0 = (bid&31)*128)
// bids [G1BLKS, +640): GEMM2 tile (ti = r>>3,  n0 = (r&7)*128), spins on
//                      g_ready[ti]==32 before touching h1.
// CTA tile M=128 x N=128, K-stage 64, 3-stage cp.async, single barrier
// per stage, 96KB smem -> 2 CTAs/SM.
// 4 warps as 2(m) x 2(n): warp tile 64x64 (square -> min LDSM traffic:
// 96KB smem traffic/stage = 192 B/HMMA vs 256 B/HMMA with 32x64 warps).
// ===================================================================

template<int KDIM>
__device__ __forceinline__ void issue_stage(const __half* __restrict__ Ag,
                                            const __half* __restrict__ Bg,
                                            int k0, int rendRel,
                                            uint32_t aBase, uint32_t bBase, int tid) {
#pragma unroll
    for (int i = 0; i < 8; i++) {           // A: 1024 cp16 (128 rows x 8 chunks)
        int idx = tid + i * 128;
        int row = idx >> 3, ch = idx & 7;
        uint32_t so = (uint32_t)row * 128 + (uint32_t)((ch ^ (row & 7)) << 4);
        cp16(aBase + so, Ag + (size_t)row * KDIM + k0 + ch * 8, row < rendRel);
    }
#pragma unroll
    for (int i = 0; i < 8; i++) {           // B: 1024 cp16
        int idx = tid + i * 128;
        int row = idx >> 3, ch = idx & 7;
        uint32_t so = (uint32_t)row * 128 + (uint32_t)((ch ^ (row & 7)) << 4);
        cp16(bBase + so, Bg + (size_t)row * KDIM + k0 + ch * 8, true);
    }
}

__device__ __forceinline__ void compute_stage64(uint32_t aB, uint32_t bB,
                                                float c[4][8][4],
                                                int wm, int wn) {
    int lane = threadIdx.x & 31;
    int lr = lane & 15;
    uint32_t khoff = (uint32_t)((lane >> 4) * 16);
#pragma unroll
    for (int kk = 0; kk < 4; kk++) {
        uint32_t low = khoff + (uint32_t)(kk * 32);
        uint32_t a[4][4];
#pragma unroll
        for (int mi = 0; mi < 4; mi++) {
            int r = wm * 64 + mi * 16 + lr;
            ldsm_x4(a[mi], aB + (uint32_t)r * 128 + (low ^ (uint32_t)((r & 7) << 4)));
        }
#pragma unroll
        for (int ni2 = 0; ni2 < 4; ni2++) {
            uint32_t q[4];
            int r = wn * 64 + ni2 * 16 + lr;
            ldsm_x4(q, bB + (uint32_t)r * 128 + (low ^ (uint32_t)((r & 7) << 4)));
            uint32_t b0[2] = {q[0], q[2]};
            uint32_t b1[2] = {q[1], q[3]};
#pragma unroll
            for (int mi = 0; mi < 4; mi++) {
                mma_16x8x16(c[mi][2 * ni2],     a[mi], b0);
                mma_16x8x16(c[mi][2 * ni2 + 1], a[mi], b1);
            }
        }
    }
}

template<int KDIM, bool SECOND>
__device__ __forceinline__ void gemm_body(int ti, int nblk, uint8_t* smem,
                                          const float* __restrict__ bias,
                                          const float* __restrict__ x,
                                          float* __restrict__ out) {
    if (ti >= g_numTiles) return;
    int e = g_tileE[ti], row0 = g_tileRow[ti], rend = g_tileEnd[ti];
    int n0 = nblk * 128;
    int rendRel = rend - row0;
    constexpr int NOUT = SECOND ? D_ : F_;

    if (SECOND) {
        // wait for the 32 GEMM1 producers of this M-tile
        if (threadIdx.x == 0) {
            while (atomicAdd(&g_ready[ti], 0) < 32) __nanosleep(64);
        }
        __syncthreads();
    }

    const __half* Ag = (SECOND ? g_h1h : g_hnh) + (size_t)row0 * KDIM;
    const __half* Bg = (SECOND ? g_w2h : g_w1h) + (size_t)e * ((size_t)F_ * D_) + (size_t)n0 * KDIM;
    const float*  brow = bias + (size_t)e * NOUT + n0;

    uint32_t sb = smem_u32(smem);
    int tid = threadIdx.x, warp = tid >> 5, lane = tid & 31;
    int wm = warp >> 1, wn = warp & 1;
    int g = lane >> 2, tg = lane & 3;

    float c[4][8][4];
#pragma unroll
    for (int mi = 0; mi < 4; mi++)
#pragma unroll
        for (int ni = 0; ni < 8; ni++)
#pragma unroll
            for (int k = 0; k < 4; k++) c[mi][ni][k] = 0.f;

    constexpr int CH = KDIM / 64;

    // prologue: stages 0..1
#pragma unroll
    for (int s = 0; s < 2; s++) {
        issue_stage<KDIM>(Ag, Bg, s * 64, rendRel,
                          sb + s * STAGE_BYTES, sb + s * STAGE_BYTES + 16384, tid);
        cp_commit();
    }

    int s_c = 0, s_p = 2;
#pragma unroll 1
    for (int i = 0; i < CH; i++) {
        cp_wait<1>();
        __syncthreads();   // single barrier per stage
        if (i + 2 < CH) {
            issue_stage<KDIM>(Ag, Bg, (i + 2) * 64, rendRel,
                              sb + s_p * STAGE_BYTES, sb + s_p * STAGE_BYTES + 16384, tid);
        }
        cp_commit();   // uniform commit keeps wait<1> aligned near the tail
        compute_stage64(sb + s_c * STAGE_BYTES, sb + s_c * STAGE_BYTES + 16384, c, wm, wn);
        s_c = (s_c == 2) ? 0 : s_c + 1;
        s_p = (s_p == 2) ? 0 : s_p + 1;
    }

    // ---------------- epilogue ----------------
    if (!SECOND) {
#pragma unroll
        for (int ni = 0; ni < 8; ni++) {
            int col = n0 + wn * 64 + ni * 8 + 2 * tg;
            float bi0 = __ldg(&brow[wn * 64 + ni * 8 + 2 * tg]);
            float bi1 = __ldg(&brow[wn * 64 + ni * 8 + 2 * tg + 1]);
#pragma unroll
            for (int mi = 0; mi < 4; mi++) {
                int r = row0 + wm * 64 + mi * 16 + g;
                *(__half2*)(g_h1h + (size_t)r * F_ + col) =
                    __floats2half2_rn(fmaxf(c[mi][ni][0] + bi0, 0.f),
                                      fmaxf(c[mi][ni][1] + bi1, 0.f));
                *(__half2*)(g_h1h + (size_t)(r + 8) * F_ + col) =
                    __floats2half2_rn(fmaxf(c[mi][ni][2] + bi0, 0.f),
                                      fmaxf(c[mi][ni][3] + bi1, 0.f));
            }
        }
        __threadfence();
        __syncthreads();
        if (tid == 0) atomicAdd(&g_ready[ti], 1);
    } else {
#pragma unroll
        for (int ni = 0; ni < 8; ni++) {
            int col = n0 + wn * 64 + ni * 8 + 2 * tg;
            float bi0 = __ldg(&brow[wn * 64 + ni * 8 + 2 * tg]);
            float bi1 = __ldg(&brow[wn * 64 + ni * 8 + 2 * tg + 1]);
#pragma unroll
            for (int mi = 0; mi < 4; mi++) {
                int r = row0 + wm * 64 + mi * 16 + g;
                if (r < rend) {
                    int t = g_srt[r];
                    float al = g_alpha[t];
                    float2 xv = *(const float2*)(x + (size_t)t * D_ + col);
                    float2 o;
                    o.x = xv.x + al * (c[mi][ni][0] + bi0);
                    o.y = xv.y + al * (c[mi][ni][1] + bi1);
                    *(float2*)(out + (size_t)t * D_ + col) = o;
                }
                if (r + 8 < rend) {
                    int t = g_srt[r + 8];
                    float al = g_alpha[t];
                    float2 xv = *(const float2*)(x + (size_t)t * D_ + col);
                    float2 o;
                    o.x = xv.x + al * (c[mi][ni][2] + bi0);
                    o.y = xv.y + al * (c[mi][ni][3] + bi1);
                    *(float2*)(out + (size_t)t * D_ + col) = o;
                }
            }
        }
    }
}

__global__ __launch_bounds__(128, 2) void fused_gemm(const float* __restrict__ b1,
                                                     const float* __restrict__ b2,
                                                     const float* __restrict__ x,
                                                     float* __restrict__ out) {
    extern __shared__ __align__(1024) uint8_t smem[];
    int bid = blockIdx.x;
    if (bid < G1BLKS) {
        gemm_body<D_, false>(bid >> 5, bid & 31, smem, b1, x, out);
    } else {
        int r = bid - G1BLKS;
        gemm_body<F_, true>(r >> 3, r & 7, smem, b2, x, out);
    }
}

// ------------------- launch -------------------
extern "C" void kernel_launch(void* const* d_in, const int* in_sizes, int n_in,
                              void* d_out, int out_size) {
    const float* x    = (const float*)d_in[0];
    const float* cent = (const float*)d_in[1];
    const float* lng  = (const float*)d_in[2];
    const float* lnb  = (const float*)d_in[3];
    const float* w1   = (const float*)d_in[4];
    const float* b1   = (const float*)d_in[5];
    const float* w2   = (const float*)d_in[6];
    const float* b2   = (const float*)d_in[7];
    float* out = (float*)d_out;

    static cudaStream_t sA = nullptr, sB = nullptr;
    static cudaEvent_t eFork = nullptr, eW1 = nullptr, eW2 = nullptr;
    if (!sA) {
        cudaStreamCreateWithFlags(&sA, cudaStreamNonBlocking);
        cudaStreamCreateWithFlags(&sB, cudaStreamNonBlocking);
        cudaEventCreateWithFlags(&eFork, cudaEventDisableTiming);
        cudaEventCreateWithFlags(&eW1, cudaEventDisableTiming);
        cudaEventCreateWithFlags(&eW2, cudaEventDisableTiming);
        cudaFuncSetAttribute(fused_gemm, cudaFuncAttributeMaxDynamicSharedMemorySize, SMEM_TOTAL);
    }

    // fork: weight converts on side streams, routing chain on main stream
    cudaEventRecord(eFork, 0);
    cudaStreamWaitEvent(sA, eFork, 0);
    cudaStreamWaitEvent(sB, eFork, 0);

    convert_kernel<<<4096, 256, 0, sA>>>(w1, 0);
    cudaEventRecord(eW1, sA);
    convert_kernel<<<4096, 256, 0, sB>>>(w2, 1);
    cudaEventRecord(eW2, sB);

    init_kernel<<<1, 128>>>();
    routing_kernel<<<T_ / 8, 256>>>(x, cent);
    scan_kernel<<<1, 1>>>();
    ln_kernel<<<T_, 256>>>(x, lng, lnb);

    // join both weight converts, then one fused GEMM launch
    cudaStreamWaitEvent(0, eW1, 0);
    cudaStreamWaitEvent(0, eW2, 0);
    fused_gemm<<<G1BLKS + 8 * MAX_TILES, 128, SMEM_TOTAL>>>(b1, b2, x, out);
}

// round 13
// speedup vs baseline: 1.6191x; 1.6191x over previous
#include <cuda_runtime.h>
#include <cuda_fp16.h>
#include <cstdint>

#define E_ 8
#define D_ 1024
#define F_ 4096
#define T_ 8192
#define TPAD (T_ + E_ * 128)     // 9216: per-expert 128-alignment padding
#define MAX_TILES 80
#define G1BLKS (32 * MAX_TILES)  // GEMM1 blocks in fused launch

#define STAGES 3
#define STAGE_BYTES 32768        // A 16KB (128x64h) + B 16KB (128x64h)
#define SMEM_TOTAL (STAGES * STAGE_BYTES)   // 98304 -> 2 CTAs/SM

// ------------------- scratch (device globals; no runtime allocs) -------------------
__device__ __half g_w1h[(size_t)E_ * F_ * D_];
__device__ __half g_w2h[(size_t)E_ * D_ * F_];
__device__ __half g_hnh[(size_t)TPAD * D_];
__device__ __half g_h1h[(size_t)TPAD * F_];
__device__ float  g_alpha[T_];
__device__ int    g_assign[T_];
__device__ int    g_srt[TPAD];
__device__ int    g_counts[E_];
__device__ int    g_offsets[E_];
__device__ int    g_cursor[E_];
__device__ int    g_tileE[MAX_TILES];
__device__ int    g_tileRow[MAX_TILES];
__device__ int    g_tileEnd[MAX_TILES];
__device__ int    g_numTiles;
__device__ int    g_ready[MAX_TILES];     // GEMM1->GEMM2 per-Mtile counters

// ------------------- ptx helpers -------------------
__device__ __forceinline__ uint32_t smem_u32(const void* p) {
    return (uint32_t)__cvta_generic_to_shared(p);
}
__device__ __forceinline__ void cp16(uint32_t dst, const void* src, bool pred) {
    asm volatile("cp.async.cg.shared.global [%0], [%1], 16, %2;\n"
                 :: "r"(dst), "l"(src), "r"(pred ? 16 : 0));
}
__device__ __forceinline__ void cp_commit() { asm volatile("cp.async.commit_group;\n"); }
template <int N>
__device__ __forceinline__ void cp_wait() { asm volatile("cp.async.wait_group %0;\n" :: "n"(N)); }

__device__ __forceinline__ void ldsm_x4(uint32_t r[4], uint32_t addr) {
    asm volatile("ldmatrix.sync.aligned.m8n8.x4.shared.b16 {%0,%1,%2,%3}, [%4];"
                 : "=r"(r[0]), "=r"(r[1]), "=r"(r[2]), "=r"(r[3]) : "r"(addr));
}

__device__ __forceinline__ void mma_16x8x16(float c[4], const uint32_t a[4], const uint32_t b[2]) {
    asm volatile(
        "mma.sync.aligned.m16n8k16.row.col.f32.f16.f16.f32 "
        "{%0,%1,%2,%3}, {%4,%5,%6,%7}, {%8,%9}, {%0,%1,%2,%3};"
        : "+f"(c[0]), "+f"(c[1]), "+f"(c[2]), "+f"(c[3])
        : "r"(a[0]), "r"(a[1]), "r"(a[2]), "r"(a[3]), "r"(b[0]), "r"(b[1]));
}

// ------------------- init -------------------
__global__ void init_kernel() {
    int i = threadIdx.x;
    if (i < E_) g_counts[i] = 0;
    if (i < MAX_TILES) g_ready[i] = 0;
    if (i + 32 < MAX_TILES) g_ready[i + 32] = 0;
    if (i + 64 < MAX_TILES) g_ready[i + 64] = 0;
}

// ------------------- fp32 -> fp16 weight conversion -------------------
__global__ void convert_kernel(const float* __restrict__ src, int which) {
    __half* dst = which ? g_w2h : g_w1h;
    size_t n4 = ((size_t)E_ * F_ * D_) / 4;
    size_t stride = (size_t)gridDim.x * blockDim.x;
    for (size_t i = (size_t)blockIdx.x * blockDim.x + threadIdx.x; i < n4; i += stride) {
        float4 v = ((const float4*)src)[i];
        ((__half2*)dst)[2 * i]     = __floats2half2_rn(v.x, v.y);
        ((__half2*)dst)[2 * i + 1] = __floats2half2_rn(v.z, v.w);
    }
}

// ------------------- routing: 2 tokens per warp -------------------
__global__ void routing_kernel(const float* __restrict__ x, const float* __restrict__ cent) {
    __shared__ float4 sc[E_][D_ / 4];
    int tid = threadIdx.x;
    for (int i = tid; i < E_ * D_ / 4; i += 256)
        ((float4*)&sc[0][0])[i] = ((const float4*)cent)[i];
    __syncthreads();

    int warp = tid >> 5, lane = tid & 31;
    int t0 = blockIdx.x * 16 + warp * 2;
    const float4* xv0 = (const float4*)(x + (size_t)t0 * D_);
    const float4* xv1 = (const float4*)(x + (size_t)(t0 + 1) * D_);

    float acc[2][E_];
#pragma unroll
    for (int e = 0; e < E_; e++) { acc[0][e] = 0.f; acc[1][e] = 0.f; }
#pragma unroll
    for (int j = 0; j < 8; j++) {
        float4 v0 = xv0[j * 32 + lane];
        float4 v1 = xv1[j * 32 + lane];
#pragma unroll
        for (int e = 0; e < E_; e++) {
            float4 c = sc[e][j * 32 + lane];
            acc[0][e] += v0.x * c.x + v0.y * c.y + v0.z * c.z + v0.w * c.w;
            acc[1][e] += v1.x * c.x + v1.y * c.y + v1.z * c.z + v1.w * c.w;
        }
    }
#pragma unroll
    for (int q = 0; q < 2; q++) {
#pragma unroll
        for (int e = 0; e < E_; e++) {
#pragma unroll
            for (int off = 16; off > 0; off >>= 1)
                acc[q][e] += __shfl_xor_sync(0xFFFFFFFFu, acc[q][e], off);
        }
        if (lane == 0) {
            int best = 0; float bv = acc[q][0];
#pragma unroll
            for (int e = 1; e < E_; e++)
                if (acc[q][e] > bv) { bv = acc[q][e]; best = e; }
            g_assign[t0 + q] = best;
            g_alpha[t0 + q] = 1.f / (1.f + expf(-bv));
            atomicAdd(&g_counts[best], 1);
        }
    }
}

// ------------------- scan -------------------
__global__ void scan_kernel() {
    if (threadIdx.x != 0) return;
    int off = 0, nt = 0;
    for (int e = 0; e < E_; e++) {
        g_offsets[e] = off;
        g_cursor[e] = off;
        int s1 = off + g_counts[e];
        for (int r = off; r < s1; r += 128) {
            g_tileE[nt]   = e;
            g_tileRow[nt] = r;
            g_tileEnd[nt] = s1;
            nt++;
        }
        off = (s1 + 127) & ~127;
    }
    g_numTiles = nt;
}

// ------------------- layernorm + scatter fused -> fp16 sorted -------------------
__global__ void ln_kernel(const float* __restrict__ x,
                          const float* __restrict__ lng,
                          const float* __restrict__ lnb) {
    int t = blockIdx.x;
    int tid = threadIdx.x;

    __shared__ int sh_s, sh_e;
    if (tid == 0) {
        int e = g_assign[t];
        int s = atomicAdd(&g_cursor[e], 1);
        g_srt[s] = t;
        sh_s = s;
        sh_e = e;
    }

    float4 v = ((const float4*)(x + (size_t)t * D_))[tid];
    float sum = v.x + v.y + v.z + v.w;
    float sq  = v.x * v.x + v.y * v.y + v.z * v.z + v.w * v.w;

    __shared__ float red[2][8];
    int warp = tid >> 5, lane = tid & 31;
#pragma unroll
    for (int off = 16; off > 0; off >>= 1) {
        sum += __shfl_xor_sync(0xFFFFFFFFu, sum, off);
        sq  += __shfl_xor_sync(0xFFFFFFFFu, sq,  off);
    }
    if (lane == 0) { red[0][warp] = sum; red[1][warp] = sq; }
    __syncthreads();
    int s = sh_s, e = sh_e;
    float tot = 0.f, totsq = 0.f;
#pragma unroll
    for (int w = 0; w < 8; w++) { tot += red[0][w]; totsq += red[1][w]; }
    float mu = tot * (1.f / D_);
    float var = totsq * (1.f / D_) - mu * mu;
    float rstd = rsqrtf(var + 1e-5f);

    float4 gg = ((const float4*)(lng + (size_t)e * D_))[tid];
    float4 bb = ((const float4*)(lnb + (size_t)e * D_))[tid];
    __half2 h0 = __floats2half2_rn((v.x - mu) * rstd * gg.x + bb.x,
                                   (v.y - mu) * rstd * gg.y + bb.y);
    __half2 h1 = __floats2half2_rn((v.z - mu) * rstd * gg.z + bb.z,
                                   (v.w - mu) * rstd * gg.w + bb.w);
    __half2* dst = (__half2*)(g_hnh + (size_t)s * D_);
    dst[2 * tid]     = h0;
    dst[2 * tid + 1] = h1;
}

// ===================================================================
// Fused grouped GEMM pair, single launch (R9 config — empirically best).
// bids [0, G1BLKS):    GEMM1 tile (ti = bid>>5, n0 = (bid&31)*128)
// bids [G1BLKS, +640): GEMM2 tile (ti = r>>3,  n0 = (r&7)*128), spins on
//                      g_ready[ti]==32 before touching h1.
// CTA tile M=128 x N=128, K-stage 64, 3-stage cp.async, single barrier
// per stage, 96KB smem -> 2 CTAs/SM. 8 warps as 4(m) x 2(n), warp 32x64.
// ===================================================================

template<int KDIM>
__device__ __forceinline__ void issue_stage(const __half* __restrict__ Ag,
                                            const __half* __restrict__ Bg,
                                            int k0, int rendRel,
                                            uint32_t aBase, uint32_t bBase, int tid) {
#pragma unroll
    for (int i = 0; i < 4; i++) {           // A: 1024 cp16 (128 rows x 8 chunks)
        int idx = tid + i * 256;
        int row = idx >> 3, ch = idx & 7;
        uint32_t so = (uint32_t)row * 128 + (uint32_t)((ch ^ (row & 7)) << 4);
        cp16(aBase + so, Ag + (size_t)row * KDIM + k0 + ch * 8, row < rendRel);
    }
#pragma unroll
    for (int i = 0; i < 4; i++) {           // B: 1024 cp16
        int idx = tid + i * 256;
        int row = idx >> 3, ch = idx & 7;
        uint32_t so = (uint32_t)row * 128 + (uint32_t)((ch ^ (row & 7)) << 4);
        cp16(bBase + so, Bg + (size_t)row * KDIM + k0 + ch * 8, true);
    }
}

__device__ __forceinline__ void compute_stage64(uint32_t aB, uint32_t bB,
                                                float c[2][8][4],
                                                int wm, int wn) {
    int lane = threadIdx.x & 31;
    int lr = lane & 15;
    uint32_t khoff = (uint32_t)((lane >> 4) * 16);
#pragma unroll
    for (int kk = 0; kk < 4; kk++) {
        uint32_t low = khoff + (uint32_t)(kk * 32);
        uint32_t a0[4], a1[4];
        {
            int r = wm * 32 + lr;
            ldsm_x4(a0, aB + (uint32_t)r * 128 + (low ^ (uint32_t)((r & 7) << 4)));
        }
        {
            int r = wm * 32 + 16 + lr;
            ldsm_x4(a1, aB + (uint32_t)r * 128 + (low ^ (uint32_t)((r & 7) << 4)));
        }
#pragma unroll
        for (int ni2 = 0; ni2 < 4; ni2++) {
            uint32_t q[4];
            int r = wn * 64 + ni2 * 16 + lr;
            ldsm_x4(q, bB + (uint32_t)r * 128 + (low ^ (uint32_t)((r & 7) << 4)));
            uint32_t b0[2] = {q[0], q[2]};
            uint32_t b1[2] = {q[1], q[3]};
            mma_16x8x16(c[0][2 * ni2],     a0, b0);
            mma_16x8x16(c[1][2 * ni2],     a1, b0);
            mma_16x8x16(c[0][2 * ni2 + 1], a0, b1);
            mma_16x8x16(c[1][2 * ni2 + 1], a1, b1);
        }
    }
}

template<int KDIM, bool SECOND>
__device__ __forceinline__ void gemm_body(int ti, int nblk, uint8_t* smem,
                                          const float* __restrict__ bias,
                                          const float* __restrict__ x,
                                          float* __restrict__ out) {
    if (ti >= g_numTiles) return;
    int e = g_tileE[ti], row0 = g_tileRow[ti], rend = g_tileEnd[ti];
    int n0 = nblk * 128;
    int rendRel = rend - row0;
    constexpr int NOUT = SECOND ? D_ : F_;

    if (SECOND) {
        // wait for the 32 GEMM1 producers of this M-tile
        if (threadIdx.x == 0) {
            while (atomicAdd(&g_ready[ti], 0) < 32) __nanosleep(64);
        }
        __syncthreads();
    }

    const __half* Ag = (SECOND ? g_h1h : g_hnh) + (size_t)row0 * KDIM;
    const __half* Bg = (SECOND ? g_w2h : g_w1h) + (size_t)e * ((size_t)F_ * D_) + (size_t)n0 * KDIM;
    const float*  brow = bias + (size_t)e * NOUT + n0;

    uint32_t sb = smem_u32(smem);
    int tid = threadIdx.x, warp = tid >> 5, lane = tid & 31;
    int wm = warp >> 1, wn = warp & 1;
    int g = lane >> 2, tg = lane & 3;

    float c[2][8][4];
#pragma unroll
    for (int mi = 0; mi < 2; mi++)
#pragma unroll
        for (int ni = 0; ni < 8; ni++)
#pragma unroll
            for (int k = 0; k < 4; k++) c[mi][ni][k] = 0.f;

    constexpr int CH = KDIM / 64;

    // prologue: stages 0..1
#pragma unroll
    for (int s = 0; s < 2; s++) {
        issue_stage<KDIM>(Ag, Bg, s * 64, rendRel,
                          sb + s * STAGE_BYTES, sb + s * STAGE_BYTES + 16384, tid);
        cp_commit();
    }

    int s_c = 0, s_p = 2;
#pragma unroll 1
    for (int i = 0; i < CH; i++) {
        cp_wait<1>();
        __syncthreads();   // single barrier per stage
        if (i + 2 < CH) {
            issue_stage<KDIM>(Ag, Bg, (i + 2) * 64, rendRel,
                              sb + s_p * STAGE_BYTES, sb + s_p * STAGE_BYTES + 16384, tid);
        }
        cp_commit();   // uniform commit keeps wait<1> aligned near the tail
        compute_stage64(sb + s_c * STAGE_BYTES, sb + s_c * STAGE_BYTES + 16384, c, wm, wn);
        s_c = (s_c == 2) ? 0 : s_c + 1;
        s_p = (s_p == 2) ? 0 : s_p + 1;
    }

    // ---------------- epilogue ----------------
    if (!SECOND) {
#pragma unroll
        for (int ni = 0; ni < 8; ni++) {
            int col = n0 + wn * 64 + ni * 8 + 2 * tg;
            float bi0 = __ldg(&brow[wn * 64 + ni * 8 + 2 * tg]);
            float bi1 = __ldg(&brow[wn * 64 + ni * 8 + 2 * tg + 1]);
#pragma unroll
            for (int mi = 0; mi < 2; mi++) {
                int r = row0 + wm * 32 + mi * 16 + g;
                *(__half2*)(g_h1h + (size_t)r * F_ + col) =
                    __floats2half2_rn(fmaxf(c[mi][ni][0] + bi0, 0.f),
                                      fmaxf(c[mi][ni][1] + bi1, 0.f));
                *(__half2*)(g_h1h + (size_t)(r + 8) * F_ + col) =
                    __floats2half2_rn(fmaxf(c[mi][ni][2] + bi0, 0.f),
                                      fmaxf(c[mi][ni][3] + bi1, 0.f));
            }
        }
        __threadfence();
        __syncthreads();
        if (tid == 0) atomicAdd(&g_ready[ti], 1);
    } else {
#pragma unroll
        for (int ni = 0; ni < 8; ni++) {
            int col = n0 + wn * 64 + ni * 8 + 2 * tg;
            float bi0 = __ldg(&brow[wn * 64 + ni * 8 + 2 * tg]);
            float bi1 = __ldg(&brow[wn * 64 + ni * 8 + 2 * tg + 1]);
#pragma unroll
            for (int mi = 0; mi < 2; mi++) {
                int r = row0 + wm * 32 + mi * 16 + g;
                if (r < rend) {
                    int t = g_srt[r];
                    float al = g_alpha[t];
                    float2 xv = *(const float2*)(x + (size_t)t * D_ + col);
                    float2 o;
                    o.x = xv.x + al * (c[mi][ni][0] + bi0);
                    o.y = xv.y + al * (c[mi][ni][1] + bi1);
                    *(float2*)(out + (size_t)t * D_ + col) = o;
                }
                if (r + 8 < rend) {
                    int t = g_srt[r + 8];
                    float al = g_alpha[t];
                    float2 xv = *(const float2*)(x + (size_t)t * D_ + col);
                    float2 o;
                    o.x = xv.x + al * (c[mi][ni][2] + bi0);
                    o.y = xv.y + al * (c[mi][ni][3] + bi1);
                    *(float2*)(out + (size_t)t * D_ + col) = o;
                }
            }
        }
    }
}

__global__ __launch_bounds__(256, 2) void fused_gemm(const float* __restrict__ b1,
                                                     const float* __restrict__ b2,
                                                     const float* __restrict__ x,
                                                     float* __restrict__ out) {
    extern __shared__ __align__(1024) uint8_t smem[];
    int bid = blockIdx.x;
    if (bid < G1BLKS) {
        gemm_body<D_, false>(bid >> 5, bid & 31, smem, b1, x, out);
    } else {
        int r = bid - G1BLKS;
        gemm_body<F_, true>(r >> 3, r & 7, smem, b2, x, out);
    }
}

// ------------------- launch -------------------
extern "C" void kernel_launch(void* const* d_in, const int* in_sizes, int n_in,
                              void* d_out, int out_size) {
    const float* x    = (const float*)d_in[0];
    const float* cent = (const float*)d_in[1];
    const float* lng  = (const float*)d_in[2];
    const float* lnb  = (const float*)d_in[3];
    const float* w1   = (const float*)d_in[4];
    const float* b1   = (const float*)d_in[5];
    const float* w2   = (const float*)d_in[6];
    const float* b2   = (const float*)d_in[7];
    float* out = (float*)d_out;

    static cudaStream_t sA = nullptr, sB = nullptr;
    static cudaEvent_t eFork = nullptr, eW1 = nullptr, eW2 = nullptr;
    if (!sA) {
        cudaStreamCreateWithFlags(&sA, cudaStreamNonBlocking);
        cudaStreamCreateWithFlags(&sB, cudaStreamNonBlocking);
        cudaEventCreateWithFlags(&eFork, cudaEventDisableTiming);
        cudaEventCreateWithFlags(&eW1, cudaEventDisableTiming);
        cudaEventCreateWithFlags(&eW2, cudaEventDisableTiming);
        cudaFuncSetAttribute(fused_gemm, cudaFuncAttributeMaxDynamicSharedMemorySize, SMEM_TOTAL);
    }

    // fork: weight converts on side streams, routing chain on main stream
    cudaEventRecord(eFork, 0);
    cudaStreamWaitEvent(sA, eFork, 0);
    cudaStreamWaitEvent(sB, eFork, 0);

    convert_kernel<<<4096, 256, 0, sA>>>(w1, 0);
    cudaEventRecord(eW1, sA);
    convert_kernel<<<4096, 256, 0, sB>>>(w2, 1);
    cudaEventRecord(eW2, sB);

    init_kernel<<<1, 128>>>();
    routing_kernel<<<T_ / 16, 256>>>(x, cent);
    scan_kernel<<<1, 1>>>();
    ln_kernel<<<T_, 256>>>(x, lng, lnb);

    // join both weight converts, then one fused GEMM launch
    cudaStreamWaitEvent(0, eW1, 0);
    cudaStreamWaitEvent(0, eW2, 0);
    fused_gemm<<<G1BLKS + 8 * MAX_TILES, 256, SMEM_TOTAL>>>(b1, b2, x, out);
}